// round 3
// baseline (speedup 1.0000x reference)
#include <cuda_runtime.h>
#include <math.h>

#define H_ 256
#define B_ 256
#define T_ 512
#define D_ 32
#define HOR_ 24
#define NQ_ 3
#define BH_ (B_*H_)
#define NBLK 128
#define SVS 34      // v-tile smem row stride (floats): 16 rows -> 16 distinct double-banks

// ---------------- device scratch ----------------
__device__ float g_zero[BH_];              // never written: initial h/c = 0
__device__ float g_h1[T_][BH_];            // layer0 outputs per t
__device__ float g_enc[T_][BH_];           // layer1 outputs per t
__device__ float g_energy[B_*T_];
__device__ float g_ctx[BH_];
__device__ float g_dh0[HOR_][BH_];         // decoder cell0 h per step (unique addr per step)
__device__ float g_dh1[HOR_][BH_];         // decoder cell1 h per step
__device__ volatile unsigned g_gen;
__device__ unsigned g_count;

// ---------------- helpers ----------------
static __device__ __forceinline__ unsigned long long fma2_(unsigned long long a,
                                                           unsigned long long b,
                                                           unsigned long long c) {
    unsigned long long d;
    asm("fma.rn.f32x2 %0, %1, %2, %3;" : "=l"(d) : "l"(a), "l"(b), "l"(c));
    return d;
}
static __device__ __forceinline__ float hsum2_(unsigned long long a) {
    float lo, hi;
    asm("mov.b64 {%0, %1}, %2;" : "=f"(lo), "=f"(hi) : "l"(a));
    return lo + hi;
}
static __device__ __forceinline__ unsigned long long lds64_(const float* p) {
    return *reinterpret_cast<const unsigned long long*>(p);
}
static __device__ __forceinline__ float sigm_(float x) { return 1.0f / (1.0f + expf(-x)); }

// software grid barrier: all NBLK blocks co-resident (NBLK <= 148, 1 block/SM)
static __device__ __forceinline__ void grid_sync() {
    __syncthreads();
    if (threadIdx.x == 0) {
        __threadfence();
        unsigned gen = g_gen;
        if (atomicAdd(&g_count, 1u) == NBLK - 1) {
            g_count = 0;
            __threadfence();
            g_gen = gen + 1;
        } else {
            while (g_gen == gen) { __nanosleep(32); }
        }
    }
    __syncthreads();
}

// ---------------- gate GEMM: 32 gate-rows x 64 batch, K chunked by 16 ----------------
// thread (jq=tid>>4, bq=tid&15) computes rows jq*4+i (i<4), cols bq+16*j (j<4),
// accumulating in f32x2 pairs along k. W resident in smem; v staged double-buffered.
static __device__ __forceinline__ void gates_compute(
    const float* __restrict__ sW, int sws,
    float* __restrict__ sV, float* __restrict__ sG, const float* __restrict__ sB,
    const float* __restrict__ in1, long long in1_str, int K1,
    const float* __restrict__ hprev, int nchunks,
    int tid, int bbase)
{
    const int jq = tid >> 4;
    const int bq = tid & 15;
    unsigned long long acc[16];
    #pragma unroll
    for (int i = 0; i < 16; i++) acc[i] = 0ull;

    const int s_row = tid >> 2;      // staging: 64 rows x 4 quads, 2 per thread
    const int s_kq  = tid & 3;

    float4 pre[2];
    #pragma unroll
    for (int r = 0; r < 2; r++) {
        int row = s_row + r * 32;
        int k = s_kq * 4;
        const float* src = (k < K1) ? (in1 + (size_t)(bbase + row) * in1_str + k)
                                    : (hprev + (size_t)(bbase + row) * H_ + (k - K1));
        pre[r] = *(const float4*)src;
    }

    for (int c = 0; c < nchunks; c++) {
        float* buf = sV + (c & 1) * (64 * SVS);
        #pragma unroll
        for (int r = 0; r < 2; r++) {
            int row = s_row + r * 32;
            float* d = &buf[row * SVS + s_kq * 4];
            *(float2*)d       = make_float2(pre[r].x, pre[r].y);
            *(float2*)(d + 2) = make_float2(pre[r].z, pre[r].w);
        }
        __syncthreads();
        if (c + 1 < nchunks) {
            #pragma unroll
            for (int r = 0; r < 2; r++) {
                int row = s_row + r * 32;
                int k = (c + 1) * 16 + s_kq * 4;
                const float* src = (k < K1) ? (in1 + (size_t)(bbase + row) * in1_str + k)
                                            : (hprev + (size_t)(bbase + row) * H_ + (k - K1));
                pre[r] = *(const float4*)src;
            }
        }
        const float* wp = sW + c * 16;
        #pragma unroll
        for (int kp = 0; kp < 8; kp++) {
            unsigned long long wv[4], vv[4];
            #pragma unroll
            for (int i = 0; i < 4; i++) wv[i] = lds64_(wp + (jq * 4 + i) * sws + 2 * kp);
            #pragma unroll
            for (int j = 0; j < 4; j++) vv[j] = lds64_(buf + (bq + 16 * j) * SVS + 2 * kp);
            #pragma unroll
            for (int i = 0; i < 4; i++)
                #pragma unroll
                for (int j = 0; j < 4; j++)
                    acc[i * 4 + j] = fma2_(wv[i], vv[j], acc[i * 4 + j]);
        }
    }
    // reduce pairs + bias into sG (rows stride 66)
    #pragma unroll
    for (int i = 0; i < 4; i++) {
        int j = jq * 4 + i;
        float bv = sB[j];
        #pragma unroll
        for (int jj = 0; jj < 4; jj++) {
            int cc = bq + 16 * jj;
            sG[j * 66 + cc] = hsum2_(acc[i * 4 + jj]) + bv;
        }
    }
}

// activation + state update; c kept in registers (crr[4]); optional scalar-input term
static __device__ __forceinline__ void lstm_activate(
    const float* __restrict__ sG, float* crr, float* __restrict__ hout,
    int tid, int hbase, int bbase,
    const float* __restrict__ cinit,
    const float* __restrict__ sWih0, const float* __restrict__ sDin)
{
    #pragma unroll
    for (int r = 0; r < 4; r++) {
        int cell = tid + r * 128;
        int b = cell >> 3, hh = cell & 7;
        float gi = sG[hh * 66 + b];
        float gf = sG[(8 + hh) * 66 + b];
        float gg = sG[(16 + hh) * 66 + b];
        float go = sG[(24 + hh) * 66 + b];
        if (sWih0) {
            float di = sDin[b];
            gi += sWih0[hh] * di;
            gf += sWih0[8 + hh] * di;
            gg += sWih0[16 + hh] * di;
            go += sWih0[24 + hh] * di;
        }
        float c = cinit ? cinit[(size_t)(bbase + b) * H_ + hbase + hh] : crr[r];
        float cn = sigm_(gf) * c + sigm_(gi) * tanhf(gg);
        crr[r] = cn;
        hout[(size_t)(bbase + b) * H_ + hbase + hh] = sigm_(go) * tanhf(cn);
    }
}

// ---------------- persistent encoder: both layers, 512 steps, 1 launch ----------------
__global__ void __launch_bounds__(128) enc_kernel(
    const float* __restrict__ x,
    const float* __restrict__ Wih0, const float* __restrict__ Whh0, const float* __restrict__ b0,
    const float* __restrict__ Wih1, const float* __restrict__ Whh1, const float* __restrict__ b1)
{
    extern __shared__ float smem[];
    float* sW0 = smem;                     // 32*290
    float* sW1 = sW0 + 32 * 290;           // 32*516
    float* sV  = sW1 + 32 * 516;           // 2*64*SVS
    float* sG  = sV + 2 * 64 * SVS;        // 32*66
    float* sB0 = sG + 32 * 66;             // 32
    float* sB1 = sB0 + 32;                 // 32

    const int tid = threadIdx.x;
    const int hbase = (blockIdx.x & 31) * 8;
    const int bbase = (blockIdx.x >> 5) * 64;

    // load this block's weight slice once: row j -> gate row (j>>3)*H + hbase + (j&7)
    for (int idx = tid; idx < 32 * 144; idx += 128) {
        int j = idx / 144, p = idx % 144;
        int grow = (j >> 3) * H_ + hbase + (j & 7);
        const float* src = (p < 16) ? (Wih0 + (size_t)grow * D_ + 2 * p)
                                    : (Whh0 + (size_t)grow * H_ + 2 * (p - 16));
        *(float2*)&sW0[j * 290 + 2 * p] = *(const float2*)src;
    }
    for (int idx = tid; idx < 32 * 256; idx += 128) {
        int j = idx >> 8, p = idx & 255;
        int grow = (j >> 3) * H_ + hbase + (j & 7);
        const float* src = (p < 128) ? (Wih1 + (size_t)grow * H_ + 2 * p)
                                     : (Whh1 + (size_t)grow * H_ + 2 * (p - 128));
        *(float2*)&sW1[j * 516 + 2 * p] = *(const float2*)src;
    }
    if (tid < 32) {
        int grow = (tid >> 3) * H_ + hbase + (tid & 7);
        sB0[tid] = b0[grow];
        sB1[tid] = b1[grow];
    }
    __syncthreads();

    float c0r[4] = {0.f, 0.f, 0.f, 0.f};
    float c1r[4] = {0.f, 0.f, 0.f, 0.f};

    for (int t = 0; t < T_; t++) {
        const float* hp0 = t ? g_h1[t - 1] : g_zero;
        gates_compute(sW0, 290, sV, sG, sB0,
                      x + (size_t)t * D_, (long long)(T_ * D_), D_, hp0, 18, tid, bbase);
        __syncthreads();
        lstm_activate(sG, c0r, g_h1[t], tid, hbase, bbase, nullptr, nullptr, nullptr);
        grid_sync();

        const float* hp1 = t ? g_enc[t - 1] : g_zero;
        gates_compute(sW1, 516, sV, sG, sB1,
                      g_h1[t], (long long)H_, H_, hp1, 32, tid, bbase);
        __syncthreads();
        lstm_activate(sG, c1r, g_enc[t], tid, hbase, bbase, nullptr, nullptr, nullptr);
        grid_sync();
    }
}

// ---------------- attention energy: warp per (b,t) ----------------
__global__ void __launch_bounds__(128) energy_kernel(
    const float* __restrict__ aW, const float* __restrict__ aV)
{
    __shared__ float sRow[4][256];
    int w = threadIdx.x >> 5, lane = threadIdx.x & 31;
    int bt = blockIdx.x * 4 + w;
    int b = bt >> 9, t = bt & 511;
    const float* row = g_enc[t] + (size_t)b * H_;
    #pragma unroll
    for (int r = 0; r < 2; r++)
        reinterpret_cast<float4*>(sRow[w])[lane + r * 32] =
            reinterpret_cast<const float4*>(row)[lane + r * 32];
    __syncwarp();
    float a0 = 0.f, a1 = 0.f, a2 = 0.f, a3 = 0.f;
    #pragma unroll 4
    for (int h = 0; h < H_; h++) {
        float e = sRow[w][h];
        float4 wv = reinterpret_cast<const float4*>(aW)[h * 32 + lane];
        a0 += e * wv.x; a1 += e * wv.y; a2 += e * wv.z; a3 += e * wv.w;
    }
    float s = tanhf(a0) * aV[lane * 4 + 0] + tanhf(a1) * aV[lane * 4 + 1]
            + tanhf(a2) * aV[lane * 4 + 2] + tanhf(a3) * aV[lane * 4 + 3];
    #pragma unroll
    for (int off = 16; off; off >>= 1) s += __shfl_xor_sync(0xffffffffu, s, off);
    if (lane == 0) g_energy[(size_t)b * T_ + t] = s;
}

// ---------------- softmax over t + context: block per b ----------------
__global__ void __launch_bounds__(256) softmax_ctx_kernel()
{
    __shared__ float sw[512];
    __shared__ float sred[9];
    int b = blockIdx.x, tid = threadIdx.x;
    float e0 = g_energy[(size_t)b * T_ + tid];
    float e1 = g_energy[(size_t)b * T_ + 256 + tid];
    float m = fmaxf(e0, e1);
    #pragma unroll
    for (int off = 16; off; off >>= 1) m = fmaxf(m, __shfl_xor_sync(0xffffffffu, m, off));
    if ((tid & 31) == 0) sred[tid >> 5] = m;
    __syncthreads();
    if (tid == 0) { float M = sred[0]; for (int i = 1; i < 8; i++) M = fmaxf(M, sred[i]); sred[8] = M; }
    __syncthreads();
    float M = sred[8];
    float p0 = expf(e0 - M), p1 = expf(e1 - M);
    float s = p0 + p1;
    #pragma unroll
    for (int off = 16; off; off >>= 1) s += __shfl_xor_sync(0xffffffffu, s, off);
    __syncthreads();
    if ((tid & 31) == 0) sred[tid >> 5] = s;
    __syncthreads();
    if (tid == 0) { float S = 0.f; for (int i = 0; i < 8; i++) S += sred[i]; sred[8] = 1.f / S; }
    __syncthreads();
    float inv = sred[8];
    sw[tid] = p0 * inv;
    sw[256 + tid] = p1 * inv;
    __syncthreads();
    float acc = 0.f;
    #pragma unroll 4
    for (int t = 0; t < T_; t++) acc += sw[t] * g_enc[t][(size_t)b * H_ + tid];
    g_ctx[(size_t)b * H_ + tid] = acc;
}

// ---------------- persistent decoder: 24 steps x 2 cells, 1 launch ----------------
__global__ void __launch_bounds__(128) dec_kernel(
    const float* __restrict__ x,
    const float* __restrict__ dWih0, const float* __restrict__ dWhh0, const float* __restrict__ db0,
    const float* __restrict__ dWih1, const float* __restrict__ dWhh1, const float* __restrict__ db1)
{
    extern __shared__ float smem[];
    float* sWd0  = smem;                    // 32*258 (Whh0 slice)
    float* sWd1  = sWd0 + 32 * 258;         // 32*516 (Wih1|Whh1 slice)
    float* sV    = sWd1 + 32 * 516;         // 2*64*SVS
    float* sG    = sV + 2 * 64 * SVS;       // 32*66
    float* sWih0 = sG + 32 * 66;            // 32 (scalar input weights)
    float* sBd0  = sWih0 + 32;              // 32
    float* sBd1  = sBd0 + 32;               // 32
    float* sDin  = sBd1 + 32;               // 64

    const int tid = threadIdx.x;
    const int hbase = (blockIdx.x & 31) * 8;
    const int bbase = (blockIdx.x >> 5) * 64;

    for (int idx = tid; idx < 32 * 128; idx += 128) {
        int j = idx >> 7, p = idx & 127;
        int grow = (j >> 3) * H_ + hbase + (j & 7);
        *(float2*)&sWd0[j * 258 + 2 * p] =
            *(const float2*)(dWhh0 + (size_t)grow * H_ + 2 * p);
    }
    for (int idx = tid; idx < 32 * 256; idx += 128) {
        int j = idx >> 8, p = idx & 255;
        int grow = (j >> 3) * H_ + hbase + (j & 7);
        const float* src = (p < 128) ? (dWih1 + (size_t)grow * H_ + 2 * p)
                                     : (dWhh1 + (size_t)grow * H_ + 2 * (p - 128));
        *(float2*)&sWd1[j * 516 + 2 * p] = *(const float2*)src;
    }
    if (tid < 32) {
        int grow = (tid >> 3) * H_ + hbase + (tid & 7);
        sWih0[tid] = dWih0[grow];
        sBd0[tid]  = db0[grow];
        sBd1[tid]  = db1[grow];
    }
    __syncthreads();

    float cd0[4], cd1[4];
    for (int s = 0; s < HOR_; s++) {
        if (tid < 64) {
            float v = (s == 0)
                ? x[((size_t)(bbase + tid) * T_ + (T_ - 1)) * D_ + (D_ - 1)]
                : g_dh1[s - 1][(size_t)(bbase + tid) * H_];
            sDin[tid] = v;
        }
        const float* hp0 = s ? g_dh0[s - 1] : g_ctx;
        gates_compute(sWd0, 258, sV, sG, sBd0,
                      g_zero, (long long)H_, 0, hp0, 16, tid, bbase);
        __syncthreads();
        lstm_activate(sG, cd0, g_dh0[s], tid, hbase, bbase,
                      (s == 0) ? g_ctx : nullptr, sWih0, sDin);
        grid_sync();

        const float* hp1 = s ? g_dh1[s - 1] : g_ctx;
        gates_compute(sWd1, 516, sV, sG, sBd1,
                      g_dh0[s], (long long)H_, H_, hp1, 32, tid, bbase);
        __syncthreads();
        lstm_activate(sG, cd1, g_dh1[s], tid, hbase, bbase,
                      (s == 0) ? g_ctx : nullptr, nullptr, nullptr);
        grid_sync();
    }
}

// ---------------- final projection: block per b ----------------
__global__ void __launch_bounds__(128) pred_kernel(
    const float* __restrict__ qW, const float* __restrict__ qb, float* __restrict__ out)
{
    __shared__ float sL[256];
    int b = blockIdx.x, tid = threadIdx.x;
    const float* last = g_dh1[HOR_ - 1];
    sL[tid] = last[(size_t)b * H_ + tid];
    sL[tid + 128] = last[(size_t)b * H_ + tid + 128];
    __syncthreads();
    if (tid < NQ_ * HOR_) {
        const float* wr = qW + (size_t)tid * H_;
        float acc = 0.f;
        #pragma unroll 8
        for (int h = 0; h < H_; h++) acc += sL[h] * wr[h];
        out[(size_t)b * (NQ_ * HOR_) + tid] = acc + qb[tid];
    }
}

// ---------------- launch ----------------
extern "C" void kernel_launch(void* const* d_in, const int* in_sizes, int n_in,
                              void* d_out, int out_size)
{
    const float* x      = (const float*)d_in[0];
    const float* e_Wih0 = (const float*)d_in[1];
    const float* e_Whh0 = (const float*)d_in[2];
    const float* e_b0   = (const float*)d_in[3];
    const float* e_Wih1 = (const float*)d_in[4];
    const float* e_Whh1 = (const float*)d_in[5];
    const float* e_b1   = (const float*)d_in[6];
    const float* d_Wih0 = (const float*)d_in[7];
    const float* d_Whh0 = (const float*)d_in[8];
    const float* d_b0   = (const float*)d_in[9];
    const float* d_Wih1 = (const float*)d_in[10];
    const float* d_Whh1 = (const float*)d_in[11];
    const float* d_b1   = (const float*)d_in[12];
    const float* aW     = (const float*)d_in[13];
    const float* aV     = (const float*)d_in[14];
    const float* qW     = (const float*)d_in[15];
    const float* qb     = (const float*)d_in[16];

    const int ENC_SMEM = (32 * 290 + 32 * 516 + 2 * 64 * SVS + 32 * 66 + 64) * 4;
    const int DEC_SMEM = (32 * 258 + 32 * 516 + 2 * 64 * SVS + 32 * 66 + 160) * 4;
    cudaFuncSetAttribute(enc_kernel, cudaFuncAttributeMaxDynamicSharedMemorySize, ENC_SMEM);
    cudaFuncSetAttribute(dec_kernel, cudaFuncAttributeMaxDynamicSharedMemorySize, DEC_SMEM);

    enc_kernel<<<NBLK, 128, ENC_SMEM>>>(x, e_Wih0, e_Whh0, e_b0, e_Wih1, e_Whh1, e_b1);
    energy_kernel<<<B_ * T_ / 4, 128>>>(aW, aV);
    softmax_ctx_kernel<<<B_, 256>>>();
    dec_kernel<<<NBLK, 128, DEC_SMEM>>>(x, d_Wih0, d_Whh0, d_b0, d_Wih1, d_Whh1, d_b1);
    pred_kernel<<<B_, 128>>>(qW, qb, (float*)d_out);
}

// round 4
// speedup vs baseline: 1.4878x; 1.4878x over previous
#include <cuda_runtime.h>
#include <math.h>

#define H_ 256
#define B_ 256
#define T_ 512
#define D_ 32
#define HOR_ 24
#define NQ_ 3
#define BH_ (B_*H_)
#define NBLK 128
#define SVS 36      // v-tile row stride (floats): 16B-aligned rows, conflict-free at 8B grain

// ---------------- device scratch ----------------
__device__ float g_zero[BH_];              // never written: initial h/c = 0
__device__ float g_h1[T_][BH_];            // layer0 outputs per t
__device__ float g_enc[T_][BH_];           // layer1 outputs per t
__device__ float g_energy[B_*T_];
__device__ float g_ctx[BH_];
__device__ float g_dh0[HOR_][BH_];
__device__ float g_dh1[HOR_][BH_];
__device__ volatile unsigned g_gen;
__device__ unsigned g_count;

// ---------------- helpers ----------------
static __device__ __forceinline__ unsigned long long fma2_(unsigned long long a,
                                                           unsigned long long b,
                                                           unsigned long long c) {
    unsigned long long d;
    asm("fma.rn.f32x2 %0, %1, %2, %3;" : "=l"(d) : "l"(a), "l"(b), "l"(c));
    return d;
}
static __device__ __forceinline__ float hsum2_(unsigned long long a) {
    float lo, hi;
    asm("mov.b64 {%0, %1}, %2;" : "=f"(lo), "=f"(hi) : "l"(a));
    return lo + hi;
}
static __device__ __forceinline__ float sigm_(float x) { return 1.0f / (1.0f + expf(-x)); }

// software grid barrier: all NBLK blocks co-resident (1 block/SM)
static __device__ __forceinline__ void grid_sync() {
    __syncthreads();
    if (threadIdx.x == 0) {
        __threadfence();
        unsigned gen = g_gen;
        if (atomicAdd(&g_count, 1u) == NBLK - 1) {
            g_count = 0;
            __threadfence();
            g_gen = gen + 1;
        } else {
            while (g_gen == gen) { }
        }
    }
    __syncthreads();
}

// ---------------- gate GEMM: 32 gate-rows x 64 batch, K split across warp-halves ----------
// 256 threads. half = tid>>7 owns K-chunks [half*nch, (half+1)*nch). Within half:
// thread (jq,bq) computes rows jq*4+i, cols bq+16*j, f32x2 pairs along k.
// W resident in smem (strides are multiples of 4 floats -> LDS.128 legal).
static __device__ __forceinline__ void gates_compute(
    const float* __restrict__ sW, int sws,
    float* __restrict__ sV, float* __restrict__ sG, const float* __restrict__ sB,
    const float* __restrict__ in1, long long in1_str, int K1,
    const float* __restrict__ hprev, int nchunks,
    int tid, int bbase)
{
    const int half = tid >> 7;
    const int tid7 = tid & 127;
    const int jq = tid7 >> 4;
    const int bq = tid7 & 15;
    const int nch = nchunks >> 1;
    const int cbase = half * nch;
    float* myV = sV + half * (2 * 64 * SVS);

    unsigned long long acc[16];
    #pragma unroll
    for (int i = 0; i < 16; i++) acc[i] = 0ull;

    const int s_row = tid7 >> 2;     // 0..31 (x2 rounds = 64 rows)
    const int s_kq  = tid7 & 3;

    float4 pre[2];
    #pragma unroll
    for (int r = 0; r < 2; r++) {
        int row = s_row + r * 32;
        int k = cbase * 16 + s_kq * 4;
        const float* src = (k < K1) ? (in1 + (size_t)(bbase + row) * in1_str + k)
                                    : (hprev + (size_t)(bbase + row) * H_ + (k - K1));
        pre[r] = *(const float4*)src;
    }

    for (int ci = 0; ci < nch; ci++) {
        float* buf = myV + (ci & 1) * (64 * SVS);
        #pragma unroll
        for (int r = 0; r < 2; r++)
            *(float4*)&buf[(s_row + r * 32) * SVS + s_kq * 4] = pre[r];
        __syncthreads();
        if (ci + 1 < nch) {
            #pragma unroll
            for (int r = 0; r < 2; r++) {
                int row = s_row + r * 32;
                int k = (cbase + ci + 1) * 16 + s_kq * 4;
                const float* src = (k < K1) ? (in1 + (size_t)(bbase + row) * in1_str + k)
                                            : (hprev + (size_t)(bbase + row) * H_ + (k - K1));
                pre[r] = *(const float4*)src;
            }
        }
        const float* wp = sW + (cbase + ci) * 16;
        #pragma unroll
        for (int k4 = 0; k4 < 4; k4++) {
            ulonglong2 wv[4], vv[4];
            #pragma unroll
            for (int i = 0; i < 4; i++)
                wv[i] = *(const ulonglong2*)(wp + (jq * 4 + i) * sws + k4 * 4);
            #pragma unroll
            for (int j = 0; j < 4; j++)
                vv[j] = *(const ulonglong2*)(buf + (bq + 16 * j) * SVS + k4 * 4);
            #pragma unroll
            for (int i = 0; i < 4; i++)
                #pragma unroll
                for (int j = 0; j < 4; j++) {
                    acc[i * 4 + j] = fma2_(wv[i].x, vv[j].x, acc[i * 4 + j]);
                    acc[i * 4 + j] = fma2_(wv[i].y, vv[j].y, acc[i * 4 + j]);
                }
        }
    }
    // merge halves into sG (row stride 66)
    if (half == 0) {
        #pragma unroll
        for (int i = 0; i < 4; i++) {
            int j = jq * 4 + i;
            float bv = sB[j];
            #pragma unroll
            for (int jj = 0; jj < 4; jj++)
                sG[j * 66 + bq + 16 * jj] = hsum2_(acc[i * 4 + jj]) + bv;
        }
    }
    __syncthreads();
    if (half == 1) {
        #pragma unroll
        for (int i = 0; i < 4; i++) {
            int j = jq * 4 + i;
            #pragma unroll
            for (int jj = 0; jj < 4; jj++)
                sG[j * 66 + bq + 16 * jj] += hsum2_(acc[i * 4 + jj]);
        }
    }
    // caller must __syncthreads() (or grid_sync) before reading sG
}

// activation + state update with 256 threads (2 cells each); c kept in registers
static __device__ __forceinline__ void lstm_activate(
    const float* __restrict__ sG, float* crr, float* __restrict__ hout,
    int tid, int hbase, int bbase,
    const float* __restrict__ cinit,
    const float* __restrict__ sWih0, const float* __restrict__ sDin)
{
    #pragma unroll
    for (int r = 0; r < 2; r++) {
        int cell = tid + r * 256;
        int b = cell >> 3, hh = cell & 7;
        float gi = sG[hh * 66 + b];
        float gf = sG[(8 + hh) * 66 + b];
        float gg = sG[(16 + hh) * 66 + b];
        float go = sG[(24 + hh) * 66 + b];
        if (sWih0) {
            float di = sDin[b];
            gi += sWih0[hh] * di;
            gf += sWih0[8 + hh] * di;
            gg += sWih0[16 + hh] * di;
            go += sWih0[24 + hh] * di;
        }
        float c = cinit ? cinit[(size_t)(bbase + b) * H_ + hbase + hh] : crr[r];
        float cn = sigm_(gf) * c + sigm_(gi) * tanhf(gg);
        crr[r] = cn;
        hout[(size_t)(bbase + b) * H_ + hbase + hh] = sigm_(go) * tanhf(cn);
    }
}

// ---------------- persistent encoder ----------------
#define SW0S 292
#define SW1S 516
__global__ void __launch_bounds__(256) enc_kernel(
    const float* __restrict__ x,
    const float* __restrict__ Wih0, const float* __restrict__ Whh0, const float* __restrict__ b0,
    const float* __restrict__ Wih1, const float* __restrict__ Whh1, const float* __restrict__ b1)
{
    extern __shared__ float smem[];
    float* sW0 = smem;                     // 32*SW0S
    float* sW1 = sW0 + 32 * SW0S;          // 32*SW1S
    float* sV  = sW1 + 32 * SW1S;          // 4*64*SVS (2 halves x 2 bufs)
    float* sG  = sV + 4 * 64 * SVS;        // 32*66
    float* sB0 = sG + 32 * 66;             // 32
    float* sB1 = sB0 + 32;                 // 32

    const int tid = threadIdx.x;
    const int hbase = (blockIdx.x & 31) * 8;
    const int bbase = (blockIdx.x >> 5) * 64;

    for (int idx = tid; idx < 32 * 144; idx += 256) {
        int j = idx / 144, p = idx % 144;
        int grow = (j >> 3) * H_ + hbase + (j & 7);
        const float* src = (p < 16) ? (Wih0 + (size_t)grow * D_ + 2 * p)
                                    : (Whh0 + (size_t)grow * H_ + 2 * (p - 16));
        *(float2*)&sW0[j * SW0S + 2 * p] = *(const float2*)src;
    }
    for (int idx = tid; idx < 32 * 256; idx += 256) {
        int j = idx >> 8, p = idx & 255;
        int grow = (j >> 3) * H_ + hbase + (j & 7);
        const float* src = (p < 128) ? (Wih1 + (size_t)grow * H_ + 2 * p)
                                     : (Whh1 + (size_t)grow * H_ + 2 * (p - 128));
        *(float2*)&sW1[j * SW1S + 2 * p] = *(const float2*)src;
    }
    if (tid < 32) {
        int grow = (tid >> 3) * H_ + hbase + (tid & 7);
        sB0[tid] = b0[grow];
        sB1[tid] = b1[grow];
    }
    __syncthreads();

    float c0r[2] = {0.f, 0.f};
    float c1r[2] = {0.f, 0.f};

    for (int t = 0; t < T_; t++) {
        const float* hp0 = t ? g_h1[t - 1] : g_zero;
        gates_compute(sW0, SW0S, sV, sG, sB0,
                      x + (size_t)t * D_, (long long)(T_ * D_), D_, hp0, 18, tid, bbase);
        __syncthreads();
        lstm_activate(sG, c0r, g_h1[t], tid, hbase, bbase, nullptr, nullptr, nullptr);
        grid_sync();   // orders h1[t] (for gates1) and enc[t-1] (from prev iter)

        const float* hp1 = t ? g_enc[t - 1] : g_zero;
        gates_compute(sW1, SW1S, sV, sG, sB1,
                      g_h1[t], (long long)H_, H_, hp1, 32, tid, bbase);
        __syncthreads();
        lstm_activate(sG, c1r, g_enc[t], tid, hbase, bbase, nullptr, nullptr, nullptr);
        // no sync: layer0 of t+1 depends only on h1[t], ordered at next grid_sync
    }
}

// ---------------- attention energy: warp per (b,t) ----------------
__global__ void __launch_bounds__(128) energy_kernel(
    const float* __restrict__ aW, const float* __restrict__ aV)
{
    __shared__ float sRow[4][256];
    int w = threadIdx.x >> 5, lane = threadIdx.x & 31;
    int bt = blockIdx.x * 4 + w;
    int b = bt >> 9, t = bt & 511;
    const float* row = g_enc[t] + (size_t)b * H_;
    #pragma unroll
    for (int r = 0; r < 2; r++)
        reinterpret_cast<float4*>(sRow[w])[lane + r * 32] =
            reinterpret_cast<const float4*>(row)[lane + r * 32];
    __syncwarp();
    float a0 = 0.f, a1 = 0.f, a2 = 0.f, a3 = 0.f;
    #pragma unroll 4
    for (int h = 0; h < H_; h++) {
        float e = sRow[w][h];
        float4 wv = reinterpret_cast<const float4*>(aW)[h * 32 + lane];
        a0 += e * wv.x; a1 += e * wv.y; a2 += e * wv.z; a3 += e * wv.w;
    }
    float s = tanhf(a0) * aV[lane * 4 + 0] + tanhf(a1) * aV[lane * 4 + 1]
            + tanhf(a2) * aV[lane * 4 + 2] + tanhf(a3) * aV[lane * 4 + 3];
    #pragma unroll
    for (int off = 16; off; off >>= 1) s += __shfl_xor_sync(0xffffffffu, s, off);
    if (lane == 0) g_energy[(size_t)b * T_ + t] = s;
}

// ---------------- softmax over t + context: block per b ----------------
__global__ void __launch_bounds__(256) softmax_ctx_kernel()
{
    __shared__ float sw[512];
    __shared__ float sred[9];
    int b = blockIdx.x, tid = threadIdx.x;
    float e0 = g_energy[(size_t)b * T_ + tid];
    float e1 = g_energy[(size_t)b * T_ + 256 + tid];
    float m = fmaxf(e0, e1);
    #pragma unroll
    for (int off = 16; off; off >>= 1) m = fmaxf(m, __shfl_xor_sync(0xffffffffu, m, off));
    if ((tid & 31) == 0) sred[tid >> 5] = m;
    __syncthreads();
    if (tid == 0) { float M = sred[0]; for (int i = 1; i < 8; i++) M = fmaxf(M, sred[i]); sred[8] = M; }
    __syncthreads();
    float M = sred[8];
    float p0 = expf(e0 - M), p1 = expf(e1 - M);
    float s = p0 + p1;
    #pragma unroll
    for (int off = 16; off; off >>= 1) s += __shfl_xor_sync(0xffffffffu, s, off);
    __syncthreads();
    if ((tid & 31) == 0) sred[tid >> 5] = s;
    __syncthreads();
    if (tid == 0) { float S = 0.f; for (int i = 0; i < 8; i++) S += sred[i]; sred[8] = 1.f / S; }
    __syncthreads();
    float inv = sred[8];
    sw[tid] = p0 * inv;
    sw[256 + tid] = p1 * inv;
    __syncthreads();
    float acc = 0.f;
    #pragma unroll 4
    for (int t = 0; t < T_; t++) acc += sw[t] * g_enc[t][(size_t)b * H_ + tid];
    g_ctx[(size_t)b * H_ + tid] = acc;
}

// ---------------- persistent decoder ----------------
#define SD0S 260
__global__ void __launch_bounds__(256) dec_kernel(
    const float* __restrict__ x,
    const float* __restrict__ dWih0, const float* __restrict__ dWhh0, const float* __restrict__ db0,
    const float* __restrict__ dWih1, const float* __restrict__ dWhh1, const float* __restrict__ db1)
{
    extern __shared__ float smem[];
    float* sWd0  = smem;                    // 32*SD0S (Whh0 slice)
    float* sWd1  = sWd0 + 32 * SD0S;        // 32*SW1S (Wih1|Whh1 slice)
    float* sV    = sWd1 + 32 * SW1S;        // 4*64*SVS
    float* sG    = sV + 4 * 64 * SVS;       // 32*66
    float* sWih0 = sG + 32 * 66;            // 32
    float* sBd0  = sWih0 + 32;              // 32
    float* sBd1  = sBd0 + 32;               // 32
    float* sDin  = sBd1 + 32;               // 64

    const int tid = threadIdx.x;
    const int hbase = (blockIdx.x & 31) * 8;
    const int bbase = (blockIdx.x >> 5) * 64;

    for (int idx = tid; idx < 32 * 128; idx += 256) {
        int j = idx >> 7, p = idx & 127;
        int grow = (j >> 3) * H_ + hbase + (j & 7);
        *(float2*)&sWd0[j * SD0S + 2 * p] =
            *(const float2*)(dWhh0 + (size_t)grow * H_ + 2 * p);
    }
    for (int idx = tid; idx < 32 * 256; idx += 256) {
        int j = idx >> 8, p = idx & 255;
        int grow = (j >> 3) * H_ + hbase + (j & 7);
        const float* src = (p < 128) ? (dWih1 + (size_t)grow * H_ + 2 * p)
                                     : (dWhh1 + (size_t)grow * H_ + 2 * (p - 128));
        *(float2*)&sWd1[j * SW1S + 2 * p] = *(const float2*)src;
    }
    if (tid < 32) {
        int grow = (tid >> 3) * H_ + hbase + (tid & 7);
        sWih0[tid] = dWih0[grow];
        sBd0[tid]  = db0[grow];
        sBd1[tid]  = db1[grow];
    }
    __syncthreads();

    float cd0[2], cd1[2];
    for (int s = 0; s < HOR_; s++) {
        const float* hp0 = s ? g_dh0[s - 1] : g_ctx;
        gates_compute(sWd0, SD0S, sV, sG, sBd0,
                      g_zero, (long long)H_, 0, hp0, 16, tid, bbase);
        grid_sync();   // orders dh1[s-1] (for sDin) + finalizes sG
        if (tid < 64) {
            sDin[tid] = (s == 0)
                ? x[((size_t)(bbase + tid) * T_ + (T_ - 1)) * D_ + (D_ - 1)]
                : g_dh1[s - 1][(size_t)(bbase + tid) * H_];
        }
        __syncthreads();
        lstm_activate(sG, cd0, g_dh0[s], tid, hbase, bbase,
                      (s == 0) ? g_ctx : nullptr, sWih0, sDin);
        grid_sync();   // orders dh0[s] before gates1

        const float* hp1 = s ? g_dh1[s - 1] : g_ctx;
        gates_compute(sWd1, SW1S, sV, sG, sBd1,
                      g_dh0[s], (long long)H_, H_, hp1, 32, tid, bbase);
        __syncthreads();
        lstm_activate(sG, cd1, g_dh1[s], tid, hbase, bbase,
                      (s == 0) ? g_ctx : nullptr, nullptr, nullptr);
    }
}

// ---------------- final projection: block per b ----------------
__global__ void __launch_bounds__(128) pred_kernel(
    const float* __restrict__ qW, const float* __restrict__ qb, float* __restrict__ out)
{
    __shared__ float sL[256];
    int b = blockIdx.x, tid = threadIdx.x;
    const float* last = g_dh1[HOR_ - 1];
    sL[tid] = last[(size_t)b * H_ + tid];
    sL[tid + 128] = last[(size_t)b * H_ + tid + 128];
    __syncthreads();
    if (tid < NQ_ * HOR_) {
        const float* wr = qW + (size_t)tid * H_;
        float acc = 0.f;
        #pragma unroll 8
        for (int h = 0; h < H_; h++) acc += sL[h] * wr[h];
        out[(size_t)b * (NQ_ * HOR_) + tid] = acc + qb[tid];
    }
}

// ---------------- launch ----------------
extern "C" void kernel_launch(void* const* d_in, const int* in_sizes, int n_in,
                              void* d_out, int out_size)
{
    const float* x      = (const float*)d_in[0];
    const float* e_Wih0 = (const float*)d_in[1];
    const float* e_Whh0 = (const float*)d_in[2];
    const float* e_b0   = (const float*)d_in[3];
    const float* e_Wih1 = (const float*)d_in[4];
    const float* e_Whh1 = (const float*)d_in[5];
    const float* e_b1   = (const float*)d_in[6];
    const float* d_Wih0 = (const float*)d_in[7];
    const float* d_Whh0 = (const float*)d_in[8];
    const float* d_b0   = (const float*)d_in[9];
    const float* d_Wih1 = (const float*)d_in[10];
    const float* d_Whh1 = (const float*)d_in[11];
    const float* d_b1   = (const float*)d_in[12];
    const float* aW     = (const float*)d_in[13];
    const float* aV     = (const float*)d_in[14];
    const float* qW     = (const float*)d_in[15];
    const float* qb     = (const float*)d_in[16];

    const int ENC_SMEM = (32 * SW0S + 32 * SW1S + 4 * 64 * SVS + 32 * 66 + 64) * 4;
    const int DEC_SMEM = (32 * SD0S + 32 * SW1S + 4 * 64 * SVS + 32 * 66 + 160) * 4;
    cudaFuncSetAttribute(enc_kernel, cudaFuncAttributeMaxDynamicSharedMemorySize, ENC_SMEM);
    cudaFuncSetAttribute(dec_kernel, cudaFuncAttributeMaxDynamicSharedMemorySize, DEC_SMEM);

    enc_kernel<<<NBLK, 256, ENC_SMEM>>>(x, e_Wih0, e_Whh0, e_b0, e_Wih1, e_Whh1, e_b1);
    energy_kernel<<<B_ * T_ / 4, 128>>>(aW, aV);
    softmax_ctx_kernel<<<B_, 256>>>();
    dec_kernel<<<NBLK, 256, DEC_SMEM>>>(x, d_Wih0, d_Whh0, d_b0, d_Wih1, d_Whh1, d_b1);
    pred_kernel<<<B_, 128>>>(qW, qb, (float*)d_out);
}